// round 4
// baseline (speedup 1.0000x reference)
#include <cuda_runtime.h>
#include <math.h>

#define IN_DIM   256
#define OUT_DIM  64
#define NUM_HEADS 8
#define BATCH    8
#define SEQ      1024
#define QKV_COLS (OUT_DIM * NUM_HEADS)   // 512
#define ROWS     (BATCH * SEQ)           // 8192

__device__ float g_Q[ROWS * QKV_COLS];
__device__ float g_K[ROWS * QKV_COLS];
__device__ float g_V[ROWS * QKV_COLS];
__device__ float g_kmax[BATCH * NUM_HEADS];   // max_k |k|^2 per (b,h)

// ---------------------------------------------------------------------------
// Kernel 1: QKV projection, 128x128 tile, 8x8/thread, double-buffered smem.
// ---------------------------------------------------------------------------
__global__ __launch_bounds__(256, 2)
void qkv_gemm_kernel(const float* __restrict__ h,
                     const float* __restrict__ Wq, const float* __restrict__ bq,
                     const float* __restrict__ Wk, const float* __restrict__ bk,
                     const float* __restrict__ Wv, const float* __restrict__ bv)
{
    const int which = blockIdx.z;
    const float* __restrict__ W    = (which == 0) ? Wq : (which == 1) ? Wk : Wv;
    const float* __restrict__ bias = (which == 0) ? bq : (which == 1) ? bk : bv;
    float* __restrict__ out        = (which == 0) ? g_Q : (which == 1) ? g_K : g_V;

    __shared__ float As[2][16][132];
    __shared__ float Bs[2][16][132];

    const int tid = threadIdx.x;
    const int tx = tid & 15;
    const int ty = tid >> 4;
    const int row0 = blockIdx.y * 128;
    const int col0 = blockIdx.x * 128;

    // loader indices (2 float4 each for A and B)
    const int ar  = (tid * 2) >> 2;          // use lin = 2*tid, 2*tid+1? keep simple:
    // lin = it*256 + tid
    float4 a_reg[2], b_reg[2];

    auto ldg_tile = [&](int k0) {
        #pragma unroll
        for (int it = 0; it < 2; it++) {
            int lin = it * 256 + tid;
            int r  = lin >> 2;               // 0..127
            int kc = (lin & 3) * 4;
            a_reg[it] = *(const float4*)&h[(size_t)(row0 + r) * IN_DIM + k0 + kc];
            int r2 = lin >> 5;               // 0..15
            int c  = (lin & 31) * 4;
            b_reg[it] = *(const float4*)&W[(size_t)(k0 + r2) * QKV_COLS + col0 + c];
        }
    };
    auto sts_tile = [&](int buf) {
        #pragma unroll
        for (int it = 0; it < 2; it++) {
            int lin = it * 256 + tid;
            int r  = lin >> 2;
            int kc = (lin & 3) * 4;
            As[buf][kc + 0][r] = a_reg[it].x;
            As[buf][kc + 1][r] = a_reg[it].y;
            As[buf][kc + 2][r] = a_reg[it].z;
            As[buf][kc + 3][r] = a_reg[it].w;
            int r2 = lin >> 5;
            int c  = (lin & 31) * 4;
            *(float4*)&Bs[buf][r2][c] = b_reg[it];
        }
    };

    float acc[8][8] = {};

    ldg_tile(0);
    sts_tile(0);
    __syncthreads();

    for (int kt = 0; kt < 16; kt++) {
        if (kt < 15) ldg_tile((kt + 1) * 16);
        const int buf = kt & 1;
        #pragma unroll
        for (int kk = 0; kk < 16; kk++) {
            float4 a0 = *(const float4*)&As[buf][kk][ty * 8];
            float4 a1 = *(const float4*)&As[buf][kk][ty * 8 + 4];
            float4 b0 = *(const float4*)&Bs[buf][kk][tx * 8];
            float4 b1 = *(const float4*)&Bs[buf][kk][tx * 8 + 4];
            float am[8] = {a0.x, a0.y, a0.z, a0.w, a1.x, a1.y, a1.z, a1.w};
            float bn[8] = {b0.x, b0.y, b0.z, b0.w, b1.x, b1.y, b1.z, b1.w};
            #pragma unroll
            for (int i = 0; i < 8; i++)
                #pragma unroll
                for (int j = 0; j < 8; j++)
                    acc[i][j] = fmaf(am[i], bn[j], acc[i][j]);
        }
        if (kt < 15) sts_tile((kt + 1) & 1);
        __syncthreads();
    }

    const int cbase = col0 + tx * 8;
    float4 bv0 = *(const float4*)&bias[cbase];
    float4 bv1 = *(const float4*)&bias[cbase + 4];
    #pragma unroll
    for (int i = 0; i < 8; i++) {
        int r = row0 + ty * 8 + i;
        float4 o0, o1;
        o0.x = acc[i][0] + bv0.x; o0.y = acc[i][1] + bv0.y;
        o0.z = acc[i][2] + bv0.z; o0.w = acc[i][3] + bv0.w;
        o1.x = acc[i][4] + bv1.x; o1.y = acc[i][5] + bv1.y;
        o1.z = acc[i][6] + bv1.z; o1.w = acc[i][7] + bv1.w;
        *(float4*)&out[(size_t)r * QKV_COLS + cbase]     = o0;
        *(float4*)&out[(size_t)r * QKV_COLS + cbase + 4] = o1;
    }
}

// ---------------------------------------------------------------------------
// Kernel 1b: max_k |k|^2 per (batch, head).  64 blocks x 256 threads.
// ---------------------------------------------------------------------------
__global__ __launch_bounds__(256)
void kmax_kernel()
{
    const int bh = blockIdx.x;
    const float* __restrict__ K =
        g_K + ((size_t)(bh >> 3) * SEQ) * QKV_COLS + (bh & 7) * OUT_DIM;

    float mx = 0.f;
    for (int r = threadIdx.x; r < SEQ; r += 256) {
        const float4* row = (const float4*)&K[(size_t)r * QKV_COLS];
        float ss = 0.f;
        #pragma unroll
        for (int j = 0; j < 16; j++) {
            float4 v = row[j];
            ss = fmaf(v.x, v.x, ss); ss = fmaf(v.y, v.y, ss);
            ss = fmaf(v.z, v.z, ss); ss = fmaf(v.w, v.w, ss);
        }
        mx = fmaxf(mx, ss);
    }
    #pragma unroll
    for (int off = 16; off >= 1; off >>= 1)
        mx = fmaxf(mx, __shfl_xor_sync(0xffffffffu, mx, off));
    __shared__ float wmx[8];
    if ((threadIdx.x & 31) == 0) wmx[threadIdx.x >> 5] = mx;
    __syncthreads();
    if (threadIdx.x == 0) {
        float m = wmx[0];
        #pragma unroll
        for (int w = 1; w < 8; w++) m = fmaxf(m, wmx[w]);
        g_kmax[bh] = m;
    }
}

// ---------------------------------------------------------------------------
// Kernel 2: fused masked attention, static-max softmax (no shuffles in loop).
// One block per (128-query tile, head, batch).  256 threads, 8x4 per thread.
// ---------------------------------------------------------------------------
#define BR 128
#define BC 64
#define RSTR 132
#define CSTR 68

__global__ __launch_bounds__(256, 2)
void attn_kernel(const int* __restrict__ adj, float* __restrict__ out)
{
    extern __shared__ float smem[];
    float* Qt = smem;                  // [64][RSTR]  Qt[d][r]
    float* Kt = Qt + 64 * RSTR;        // [64][CSTR]  Kt[d][c]
    float* Vs = Kt + 64 * CSTR;        // [64][CSTR]  Vs[c][d]
    float* Ps = Vs + 64 * CSTR;        // [128][CSTR] Ps[r][c]
    float* Mrow = Ps + 128 * CSTR;     // [128] static row max

    const int b  = blockIdx.z;
    const int hd = blockIdx.y;
    const int q0 = blockIdx.x * BR;

    const int tid = threadIdx.x;
    const int tx = tid & 15;
    const int ty = tid >> 4;

    const float* __restrict__ Q = g_Q + ((size_t)b * SEQ) * QKV_COLS + hd * OUT_DIM;
    const float* __restrict__ K = g_K + ((size_t)b * SEQ) * QKV_COLS + hd * OUT_DIM;
    const float* __restrict__ V = g_V + ((size_t)b * SEQ) * QKV_COLS + hd * OUT_DIM;

    float4 kr[4], vr[4];
    auto ldg_kv = [&](int m0) {
        #pragma unroll
        for (int it = 0; it < 4; it++) {
            int lin = it * 256 + tid;
            int r = lin >> 4;
            int d = (lin & 15) * 4;
            kr[it] = *(const float4*)&K[(size_t)(m0 + r) * QKV_COLS + d];
            vr[it] = *(const float4*)&V[(size_t)(m0 + r) * QKV_COLS + d];
        }
    };
    auto sts_k = [&]() {
        #pragma unroll
        for (int it = 0; it < 4; it++) {
            int lin = it * 256 + tid;
            int r = lin >> 4;
            int d = (lin & 15) * 4;
            Kt[(d + 0) * CSTR + r] = kr[it].x;
            Kt[(d + 1) * CSTR + r] = kr[it].y;
            Kt[(d + 2) * CSTR + r] = kr[it].z;
            Kt[(d + 3) * CSTR + r] = kr[it].w;
        }
    };
    auto sts_v = [&]() {
        #pragma unroll
        for (int it = 0; it < 4; it++) {
            int lin = it * 256 + tid;
            int r = lin >> 4;
            int d = (lin & 15) * 4;
            *(float4*)&Vs[r * CSTR + d] = vr[it];
        }
    };

    // ---- prologue: Q tile transposed + first K/V tile ----
    #pragma unroll
    for (int it = 0; it < 8; it++) {
        int lin = it * 256 + tid;
        int r = lin >> 4;
        int d = (lin & 15) * 4;
        float4 q = *(const float4*)&Q[(size_t)(q0 + r) * QKV_COLS + d];
        Qt[(d + 0) * RSTR + r] = q.x;
        Qt[(d + 1) * RSTR + r] = q.y;
        Qt[(d + 2) * RSTR + r] = q.z;
        Qt[(d + 3) * RSTR + r] = q.w;
    }
    ldg_kv(0);
    __syncthreads();

    // static per-row max bound: |q| * max|k| * scale  (Cauchy-Schwarz)
    const float kmax2 = g_kmax[b * NUM_HEADS + hd];
    if (tid < 128) {
        float ss = 0.f;
        #pragma unroll 16
        for (int d = 0; d < 64; d++) {
            float q = Qt[d * RSTR + tid];
            ss = fmaf(q, q, ss);
        }
        Mrow[tid] = sqrtf(ss * kmax2) * 0.125f;
    }
    sts_k();
    sts_v();
    __syncthreads();

    const float scale = 0.125f;
    const float NEG = -1.0e30f;

    float l[8], acc[8][4];
    float m_i[8];
    #pragma unroll
    for (int i = 0; i < 8; i++) {
        l[i] = 0.f;
        m_i[i] = Mrow[ty * 8 + i];
        #pragma unroll
        for (int j = 0; j < 4; j++) acc[i][j] = 0.f;
    }

    for (int t = 0; t < SEQ / BC; t++) {
        const int m0 = t * BC;
        const bool more = (t < SEQ / BC - 1);

        // ---- S = Q K^T (8x4 per thread) ----
        float s[8][4] = {};
        #pragma unroll 8
        for (int kk = 0; kk < 64; kk++) {
            float4 q0v = *(const float4*)&Qt[kk * RSTR + ty * 8];
            float4 q1v = *(const float4*)&Qt[kk * RSTR + ty * 8 + 4];
            float4 kv  = *(const float4*)&Kt[kk * CSTR + tx * 4];
            float qa[8] = {q0v.x, q0v.y, q0v.z, q0v.w, q1v.x, q1v.y, q1v.z, q1v.w};
            float ka[4] = {kv.x, kv.y, kv.z, kv.w};
            #pragma unroll
            for (int i = 0; i < 8; i++)
                #pragma unroll
                for (int j = 0; j < 4; j++)
                    s[i][j] = fmaf(qa[i], ka[j], s[i][j]);
        }

        // prefetch next K/V while crossbar/MUFU work happens
        if (more) ldg_kv(m0 + BC);

        // ---- mask + exp(s*scale - m) + partial l + stage P ----
        #pragma unroll
        for (int i = 0; i < 8; i++) {
            const float m = m_i[i];
            int4 a4 = *(const int4*)&adj[(size_t)(q0 + ty * 8 + i) * SEQ + m0 + tx * 4];
            float p0 = __expf(fmaf(a4.x ? s[i][0] : NEG, scale, -m));
            float p1 = __expf(fmaf(a4.y ? s[i][1] : NEG, scale, -m));
            float p2 = __expf(fmaf(a4.z ? s[i][2] : NEG, scale, -m));
            float p3 = __expf(fmaf(a4.w ? s[i][3] : NEG, scale, -m));
            l[i] += (p0 + p1) + (p2 + p3);
            *(float4*)&Ps[(ty * 8 + i) * CSTR + tx * 4] = make_float4(p0, p1, p2, p3);
        }
        __syncthreads();

        if (more) sts_k();          // Kt dead after QK; safe post-barrier

        // ---- O += P V ----
        #pragma unroll 2
        for (int c4 = 0; c4 < BC / 4; c4++) {
            float4 vv[4];
            #pragma unroll
            for (int j = 0; j < 4; j++)
                vv[j] = *(const float4*)&Vs[(c4 * 4 + j) * CSTR + tx * 4];
            #pragma unroll
            for (int i = 0; i < 8; i++) {
                float4 p = *(const float4*)&Ps[(ty * 8 + i) * CSTR + c4 * 4];
                acc[i][0] = fmaf(p.x, vv[0].x, acc[i][0]);
                acc[i][1] = fmaf(p.x, vv[0].y, acc[i][1]);
                acc[i][2] = fmaf(p.x, vv[0].z, acc[i][2]);
                acc[i][3] = fmaf(p.x, vv[0].w, acc[i][3]);
                acc[i][0] = fmaf(p.y, vv[1].x, acc[i][0]);
                acc[i][1] = fmaf(p.y, vv[1].y, acc[i][1]);
                acc[i][2] = fmaf(p.y, vv[1].z, acc[i][2]);
                acc[i][3] = fmaf(p.y, vv[1].w, acc[i][3]);
                acc[i][0] = fmaf(p.z, vv[2].x, acc[i][0]);
                acc[i][1] = fmaf(p.z, vv[2].y, acc[i][1]);
                acc[i][2] = fmaf(p.z, vv[2].z, acc[i][2]);
                acc[i][3] = fmaf(p.z, vv[2].w, acc[i][3]);
                acc[i][0] = fmaf(p.w, vv[3].x, acc[i][0]);
                acc[i][1] = fmaf(p.w, vv[3].y, acc[i][1]);
                acc[i][2] = fmaf(p.w, vv[3].z, acc[i][2]);
                acc[i][3] = fmaf(p.w, vv[3].w, acc[i][3]);
            }
        }
        if (more) {
            __syncthreads();        // PV done; Vs free
            sts_v();                // covered by next tile's post-Ps barrier
        }
    }

    // ---- epilogue: reduce l across the 16 lanes of each row, normalize ----
    #pragma unroll
    for (int i = 0; i < 8; i++) {
        float li = l[i];
        #pragma unroll
        for (int off = 8; off >= 1; off >>= 1)
            li += __shfl_xor_sync(0xffffffffu, li, off);
        float inv = 1.0f / li;
        int n = q0 + ty * 8 + i;
        float4 o;
        o.x = acc[i][0] * inv;
        o.y = acc[i][1] * inv;
        o.z = acc[i][2] * inv;
        o.w = acc[i][3] * inv;
        *(float4*)&out[((size_t)(b * SEQ + n)) * QKV_COLS + hd * OUT_DIM + tx * 4] = o;
    }
}

// ---------------------------------------------------------------------------
// Launch
// ---------------------------------------------------------------------------
extern "C" void kernel_launch(void* const* d_in, const int* in_sizes, int n_in,
                              void* d_out, int out_size)
{
    const int*   adj = (const int*)  d_in[0];
    const float* h   = (const float*)d_in[1];
    const float* Wq  = (const float*)d_in[2];
    const float* bq  = (const float*)d_in[3];
    const float* Wk  = (const float*)d_in[4];
    const float* bk  = (const float*)d_in[5];
    const float* Wv  = (const float*)d_in[6];
    const float* bv  = (const float*)d_in[7];
    float* out = (float*)d_out;

    qkv_gemm_kernel<<<dim3(4, 64, 3), 256>>>(h, Wq, bq, Wk, bk, Wv, bv);
    kmax_kernel<<<64, 256>>>();

    const int smem_bytes = (64 * RSTR + 64 * CSTR + 64 * CSTR + 128 * CSTR + 128)
                           * (int)sizeof(float);   // ~103.9 KB
    static bool attr_set = false;
    if (!attr_set) {
        cudaFuncSetAttribute(attn_kernel,
                             cudaFuncAttributeMaxDynamicSharedMemorySize, smem_bytes);
        attr_set = true;
    }
    attn_kernel<<<dim3(SEQ / BR, NUM_HEADS, BATCH), 256, smem_bytes>>>(adj, out);
}